// round 15
// baseline (speedup 1.0000x reference)
#include <cuda_runtime.h>
#include <cuda_fp16.h>
#include <mma.h>
#include <math.h>
#include <stdint.h>

using namespace nvcuda;

// ---------------------------------------------------------------------------
// Problem max sizes
// ---------------------------------------------------------------------------
#define NMAX   50000
#define MMAX   20000
#define NNZMAX 400000
#define HMAX   256
#define WTOTAL 393216
#define SCAN_TILE 4096
#define SCAN_MAXTILES 16

// ---------------------------------------------------------------------------
// Scratch (device globals)
// ---------------------------------------------------------------------------
__device__ float g_score0[NMAX];
__device__ float g_score1[NMAX];

__device__ __half g_Xinit[NMAX * HMAX];
__device__ __half g_Xfeat[NMAX * HMAX];
__device__ __half g_Ye2  [MMAX * HMAX];
__device__ __half g_A [NMAX * HMAX];
__device__ __half g_B [NMAX * HMAX];
__device__ __half g_Ye[MMAX * HMAX];
__device__ __half g_S [MMAX * 64];
__device__ __half g_Wh[WTOTAL];

// CSR structures
__device__ int g_e_rowptr[MMAX + 1];
__device__ int g_v_rowptr[NMAX + 1];
__device__ int g_e_cursor[MMAX];
__device__ int g_v_cursor[NMAX];
__device__ int g_cntE[MMAX];
__device__ int g_cntV[NMAX];
__device__ int g_eV[NNZMAX];
__device__ int g_vE[NNZMAX];
__device__ int g_bsumE[SCAN_MAXTILES];
__device__ int g_bsumV[SCAN_MAXTILES];

// ---------------------------------------------------------------------------
// Helpers
// ---------------------------------------------------------------------------
__device__ __forceinline__ float eluf(float x)  { return x > 0.f ? x : expm1f(x); }
__device__ __forceinline__ float leakyf(float x){ return x > 0.f ? x : 0.2f * x; }

__device__ __forceinline__ uint32_t smem_to_u32(const void* p) {
    uint32_t a;
    asm("{ .reg .u64 t; cvta.to.shared.u64 t, %1; cvt.u32.u64 %0, t; }" : "=r"(a) : "l"(p));
    return a;
}
__device__ __forceinline__ void cp_async16(uint32_t dst, const void* src, int sz) {
    asm volatile("cp.async.cg.shared.global [%0], [%1], 16, %2;"
                 :: "r"(dst), "l"(src), "r"(sz) : "memory");
}
#define CP_COMMIT() asm volatile("cp.async.commit_group;" ::: "memory")
#define CP_WAIT(n)  asm volatile("cp.async.wait_group %0;" :: "n"(n) : "memory")

__device__ __forceinline__ void conv_store4(float4 v, __half* p) {
    __half2 h0 = __floats2half2_rn(v.x, v.y);
    __half2 h1 = __floats2half2_rn(v.z, v.w);
    uint2 u;
    u.x = *reinterpret_cast<unsigned*>(&h0);
    u.y = *reinterpret_cast<unsigned*>(&h1);
    *reinterpret_cast<uint2*>(p) = u;
}

__global__ void tohalf_kernel(const float* __restrict__ x, __half* __restrict__ out, long n4)
{
    long i = (long)blockIdx.x * blockDim.x + threadIdx.x;
    long stride = (long)gridDim.x * blockDim.x;
    for (; i < n4; i += stride)
        conv_store4(reinterpret_cast<const float4*>(x)[i], out + 4 * i);
}

struct ConvJob { const float* src; __half* dst; long n4; };
struct ConvJobs {
    ConvJob j[8];
    float* sc0; float* sc1; int n_sc;
};
__global__ void conv_pack_kernel(ConvJobs jobs)
{
    int job = blockIdx.y;
    long i = (long)blockIdx.x * blockDim.x + threadIdx.x;
    long stride = (long)gridDim.x * blockDim.x;
    if (job < 8) {
        const float* src = jobs.j[job].src;
        __half* dst = jobs.j[job].dst;
        long n4 = jobs.j[job].n4;
        for (; i < n4; i += stride)
            conv_store4(reinterpret_cast<const float4*>(src)[i], dst + 4 * i);
    } else {
        for (; i < jobs.n_sc; i += stride) {
            jobs.sc0[i] = 0.f;
            jobs.sc1[i] = 0.f;
        }
    }
}

__global__ void fill2_int(int* __restrict__ p0, int n0, int* __restrict__ p1, int n1)
{
    int i = blockIdx.x * blockDim.x + threadIdx.x;
    int stride = gridDim.x * blockDim.x;
    for (int k = i; k < n0; k += stride) p0[k] = 0;
    for (int k = i; k < n1; k += stride) p1[k] = 0;
}

// ---------------------------------------------------------------------------
// CSR construction
// ---------------------------------------------------------------------------
__global__ void count_kernel(const int* __restrict__ V, const int* __restrict__ E,
                             int* __restrict__ cntV, int* __restrict__ cntE, int nnz)
{
    int i = blockIdx.x * blockDim.x + threadIdx.x;
    if (i >= nnz) return;
    atomicAdd(&cntE[E[i]], 1);
    atomicAdd(&cntV[V[i]], 1);
}

// Multi-block 3-phase scan.
// Phase A: per-tile sums (grid.x tiles, grid.y selects array)
__global__ __launch_bounds__(256)
void scanA_kernel(const int* __restrict__ cntE, int lenE, int* __restrict__ bsumE,
                  const int* __restrict__ cntV, int lenV, int* __restrict__ bsumV)
{
    const int* cnt = blockIdx.y ? cntV : cntE;
    int len = blockIdx.y ? lenV : lenE;
    int* bsum = blockIdx.y ? bsumV : bsumE;
    int tile = blockIdx.x;
    int beg = tile * SCAN_TILE;
    if (beg >= len) return;
    int lim = beg + SCAN_TILE < len ? beg + SCAN_TILE : len;

    const int tid = threadIdx.x, lane = tid & 31, wid = tid >> 5;
    int s = 0;
    for (int i = beg + tid * 4; i < lim; i += 1024) {
        int4 v = *reinterpret_cast<const int4*>(cnt + i);
        s += v.x + v.y + v.z + v.w;
    }
#pragma unroll
    for (int o = 16; o > 0; o >>= 1) s += __shfl_xor_sync(0xffffffffu, s, o);
    __shared__ int ws[8];
    if (lane == 0) ws[wid] = s;
    __syncthreads();
    if (tid == 0) {
        int t = 0;
#pragma unroll
        for (int k = 0; k < 8; k++) t += ws[k];
        bsum[tile] = t;
    }
}

// Phase B: inclusive scan of blocksums (<= SCAN_MAXTILES each), one tiny block
__global__ void scanB_kernel(int* __restrict__ bsumE, int nE,
                             int* __restrict__ bsumV, int nV)
{
    int lane = threadIdx.x & 31;
    if (threadIdx.x < 32) {
        int v = (lane < nE) ? bsumE[lane] : 0;
#pragma unroll
        for (int o = 1; o < 32; o <<= 1) {
            int u = __shfl_up_sync(0xffffffffu, v, o);
            if (lane >= o) v += u;
        }
        if (lane < nE) bsumE[lane] = v;
    } else {
        int v = (lane < nV) ? bsumV[lane] : 0;
#pragma unroll
        for (int o = 1; o < 32; o <<= 1) {
            int u = __shfl_up_sync(0xffffffffu, v, o);
            if (lane >= o) v += u;
        }
        if (lane < nV) bsumV[lane] = v;
    }
}

// Phase C: per-tile prefix write. 8 warps x 512-elem regions, pipelined carry.
__global__ __launch_bounds__(256)
void scanC_kernel(const int* __restrict__ cntE, int* __restrict__ e_rowptr,
                  int* __restrict__ e_cursor, int lenE, const int* __restrict__ bsumE, int nE,
                  const int* __restrict__ cntV, int* __restrict__ v_rowptr,
                  int* __restrict__ v_cursor, int lenV, const int* __restrict__ bsumV, int nV)
{
    const int* cnt; int* rowptr; int* cursor; int len; const int* bsum; int nb;
    if (blockIdx.y) { cnt = cntV; rowptr = v_rowptr; cursor = v_cursor; len = lenV; bsum = bsumV; nb = nV; }
    else            { cnt = cntE; rowptr = e_rowptr; cursor = e_cursor; len = lenE; bsum = bsumE; nb = nE; }
    int tile = blockIdx.x;
    int beg = tile * SCAN_TILE;
    if (beg >= len) return;
    int lim = beg + SCAN_TILE < len ? beg + SCAN_TILE : len;
    int tbase = (tile == 0) ? 0 : bsum[tile - 1];

    const int tid = threadIdx.x, lane = tid & 31, wid = tid >> 5;
    const int wbeg = beg + wid * 512;
    const int wlim = (wbeg + 512 < lim) ? wbeg + 512 : lim;

    // per-warp sums within tile
    __shared__ int ws[9];
    int s = 0;
    for (int i = wbeg + lane * 4; i < wlim; i += 128) {
        int4 v = *reinterpret_cast<const int4*>(cnt + i);
        s += v.x + v.y + v.z + v.w;
    }
#pragma unroll
    for (int o = 16; o > 0; o >>= 1) s += __shfl_xor_sync(0xffffffffu, s, o);
    if (lane == 0) ws[wid + 1] = s;
    if (tid == 0) ws[0] = 0;
    __syncthreads();
    if (tid == 0) {
#pragma unroll
        for (int k = 1; k < 9; k++) ws[k] += ws[k - 1];
    }
    __syncthreads();

    // pipelined prefix write over 4 chunks
    int carry = tbase + ws[wid];
    int i = wbeg + lane * 4;
    int4 v = (i < wlim) ? *reinterpret_cast<const int4*>(cnt + i) : make_int4(0, 0, 0, 0);
    for (int i0 = wbeg; i0 < wlim; i0 += 128) {
        int inext = i + 128;
        int4 vn = (inext < wlim) ? *reinterpret_cast<const int4*>(cnt + inext)
                                 : make_int4(0, 0, 0, 0);
        int t1 = v.x + v.y, t2 = t1 + v.z, t3 = t2 + v.w;
        int inc = t3;
#pragma unroll
        for (int o = 1; o < 32; o <<= 1) {
            int u = __shfl_up_sync(0xffffffffu, inc, o);
            if (lane >= o) inc += u;
        }
        int excl = carry + inc - t3;
        if (i < wlim) {
            rowptr[i + 0] = excl;       cursor[i + 0] = excl;
            rowptr[i + 1] = excl + v.x; cursor[i + 1] = excl + v.x;
            rowptr[i + 2] = excl + t1;  cursor[i + 2] = excl + t1;
            rowptr[i + 3] = excl + t2;  cursor[i + 3] = excl + t2;
        }
        carry += __shfl_sync(0xffffffffu, inc, 31);
        v = vn;
        i = inext;
    }
    if (tile == nb - 1 && tid == 0) rowptr[len] = bsum[nb - 1];
}

__global__ void fill_eV_kernel(const int* __restrict__ V, const int* __restrict__ E,
                               int* __restrict__ e_cursor, int* __restrict__ eV, int nnz)
{
    int i = blockIdx.x * blockDim.x + threadIdx.x;
    if (i >= nnz) return;
    int pe = atomicAdd(&e_cursor[E[i]], 1);
    eV[pe] = V[i];
}
__global__ void fill_vE_kernel(const int* __restrict__ V, const int* __restrict__ E,
                               int* __restrict__ v_cursor, int* __restrict__ vE, int nnz)
{
    int i = blockIdx.x * blockDim.x + threadIdx.x;
    if (i >= nnz) return;
    int pv = atomicAdd(&v_cursor[V[i]], 1);
    vE[pv] = E[i];
}

// ---------------------------------------------------------------------------
// fp16 tensor-core GEMM (fp16 weights, fp16 out), cp.async double buffered.
// ---------------------------------------------------------------------------
struct GemmStage {
    __half A[128][40];
    __half B[32][136];
};
static constexpr int GEMM_SMEM = 2 * sizeof(GemmStage);   // 37888

__global__ __launch_bounds__(256, 2)
void gemm_fp16(const __half* __restrict__ A1, int K1,
               const __half* __restrict__ A2, int K2,
               const __half* __restrict__ Bg,
               const float* __restrict__ bias,
               __half* __restrict__ Ch,
               const float* __restrict__ avec, float* __restrict__ score_out,
               int M, int N)
{
    extern __shared__ char smem_raw[];
    GemmStage* st = reinterpret_cast<GemmStage*>(smem_raw);

    const int tid  = threadIdx.x;
    const int wid  = tid >> 5, lane = tid & 31;
    const int wm   = wid >> 1, wn = wid & 1;
    const int row0 = blockIdx.y * 128;
    const int col0 = blockIdx.x * 128;
    const int K = K1 + K2, nch = K >> 5;

    wmma::fragment<wmma::accumulator, 16, 16, 16, float> acc[2][4];
#pragma unroll
    for (int mt = 0; mt < 2; mt++)
#pragma unroll
        for (int nt = 0; nt < 4; nt++) wmma::fill_fragment(acc[mt][nt], 0.f);

    auto prefetch = [&](int c, int s) {
        const int k0 = c * 32;
        const __half* a; int lda, col;
        if (k0 < K1) { a = A1; lda = K1; col = k0; }
        else         { a = A2; lda = K2; col = k0 - K1; }
#pragma unroll
        for (int t = 0; t < 2; t++) {
            int u = tid + t * 256, r = u >> 2, q = u & 3;
            int gr = row0 + r;
            int sz = (gr < M) ? 16 : 0;
            size_t off = (size_t)(gr < M ? gr : 0) * lda + col + q * 8;
            cp_async16(smem_to_u32(&st[s].A[r][q * 8]), a + off, sz);
        }
#pragma unroll
        for (int t = 0; t < 2; t++) {
            int u = tid + t * 256, r = u >> 4, q = u & 15;
            size_t off = (size_t)(k0 + r) * N + col0 + q * 8;
            cp_async16(smem_to_u32(&st[s].B[r][q * 8]), Bg + off, 16);
        }
    };

    prefetch(0, 0);
    CP_COMMIT();

    for (int c = 0; c < nch; c++) {
        const int s = c & 1;
        if (c + 1 < nch) {
            prefetch(c + 1, s ^ 1);
            CP_COMMIT();
            CP_WAIT(1);
        } else {
            CP_WAIT(0);
        }
        __syncthreads();

#pragma unroll
        for (int ks = 0; ks < 2; ks++) {
            wmma::fragment<wmma::matrix_a, 16, 16, 16, __half, wmma::row_major> af[2];
#pragma unroll
            for (int mt = 0; mt < 2; mt++)
                wmma::load_matrix_sync(af[mt], &st[s].A[wm * 32 + mt * 16][ks * 16], 40);
#pragma unroll
            for (int nt = 0; nt < 4; nt++) {
                wmma::fragment<wmma::matrix_b, 16, 16, 16, __half, wmma::row_major> bf;
                wmma::load_matrix_sync(bf, &st[s].B[ks * 16][wn * 64 + nt * 16], 136);
#pragma unroll
                for (int mt = 0; mt < 2; mt++)
                    wmma::mma_sync(acc[mt][nt], af[mt], bf, acc[mt][nt]);
            }
        }
        __syncthreads();
    }

    float* stg = reinterpret_cast<float*>(smem_raw) + wid * 320;
#pragma unroll
    for (int mt = 0; mt < 2; mt++) {
        float sacc = 0.f;
        int grow_last = -1;
#pragma unroll
        for (int nt = 0; nt < 4; nt++) {
            wmma::store_matrix_sync(stg, acc[mt][nt], 20, wmma::mem_row_major);
            __syncwarp();
            int r = lane >> 1, cofs = (lane & 1) * 8;
            int gr = row0 + wm * 32 + mt * 16 + r;
            int gc = col0 + wn * 64 + nt * 16 + cofs;
            grow_last = gr;
            if (gr < M) {
                float o[8];
#pragma unroll
                for (int j = 0; j < 8; j++) o[j] = stg[r * 20 + cofs + j] + __ldg(&bias[gc + j]);
                if (score_out) {
#pragma unroll
                    for (int j = 0; j < 8; j++) sacc += o[j] * __ldg(&avec[gc + j]);
                }
                uint4 u;
                __half2 p0 = __floats2half2_rn(o[0], o[1]);
                __half2 p1 = __floats2half2_rn(o[2], o[3]);
                __half2 p2 = __floats2half2_rn(o[4], o[5]);
                __half2 p3 = __floats2half2_rn(o[6], o[7]);
                u.x = *reinterpret_cast<unsigned*>(&p0);
                u.y = *reinterpret_cast<unsigned*>(&p1);
                u.z = *reinterpret_cast<unsigned*>(&p2);
                u.w = *reinterpret_cast<unsigned*>(&p3);
                *reinterpret_cast<uint4*>(Ch + (size_t)gr * N + gc) = u;
            }
            __syncwarp();
        }
        if (score_out && grow_last >= 0 && grow_last < M)
            atomicAdd(&score_out[grow_last], sacc);
    }
}

// ---------------------------------------------------------------------------
// Fused v2e: segment softmax + weighted fp16 gather + elu -> fp16 out (x4)
// ---------------------------------------------------------------------------
__global__ __launch_bounds__(256)
void v2e_softmax_kernel(const __half* __restrict__ Xfeat, const float* __restrict__ score,
                        const int* __restrict__ e_rowptr, const int* __restrict__ eV,
                        __half* __restrict__ Ye, int M, int H)
{
    int warp = (blockIdx.x * blockDim.x + threadIdx.x) >> 5;
    int lane = threadIdx.x & 31;
    if (warp >= M) return;
    const int beg = e_rowptr[warp];
    const int end = e_rowptr[warp + 1];

    float m = -1e30f;
    for (int j = beg + lane; j < end; j += 32)
        m = fmaxf(m, leakyf(__ldg(&score[eV[j]])));
#pragma unroll
    for (int o = 16; o > 0; o >>= 1) m = fmaxf(m, __shfl_xor_sync(0xffffffffu, m, o));

    float den = 0.f;
    for (int j = beg + lane; j < end; j += 32)
        den += expf(leakyf(__ldg(&score[eV[j]])) - m);
#pragma unroll
    for (int o = 16; o > 0; o >>= 1) den += __shfl_xor_sync(0xffffffffu, den, o);
    float invden = (end > beg) ? 1.f / den : 0.f;

    float acc[8];
#pragma unroll
    for (int k = 0; k < 8; k++) acc[k] = 0.f;

    int j = beg;
    for (; j + 4 <= end; j += 4) {
        int v0 = eV[j], v1 = eV[j + 1], v2 = eV[j + 2], v3 = eV[j + 3];
        float w0 = expf(leakyf(__ldg(&score[v0])) - m) * invden;
        float w1 = expf(leakyf(__ldg(&score[v1])) - m) * invden;
        float w2 = expf(leakyf(__ldg(&score[v2])) - m) * invden;
        float w3 = expf(leakyf(__ldg(&score[v3])) - m) * invden;
        uint4 u0 = __ldg(reinterpret_cast<const uint4*>(Xfeat + (size_t)v0 * H) + lane);
        uint4 u1 = __ldg(reinterpret_cast<const uint4*>(Xfeat + (size_t)v1 * H) + lane);
        uint4 u2 = __ldg(reinterpret_cast<const uint4*>(Xfeat + (size_t)v2 * H) + lane);
        uint4 u3 = __ldg(reinterpret_cast<const uint4*>(Xfeat + (size_t)v3 * H) + lane);
        const __half2* h0 = reinterpret_cast<const __half2*>(&u0);
        const __half2* h1 = reinterpret_cast<const __half2*>(&u1);
        const __half2* h2 = reinterpret_cast<const __half2*>(&u2);
        const __half2* h3 = reinterpret_cast<const __half2*>(&u3);
#pragma unroll
        for (int k = 0; k < 4; k++) {
            float2 f0 = __half22float2(h0[k]);
            float2 f1 = __half22float2(h1[k]);
            float2 f2 = __half22float2(h2[k]);
            float2 f3 = __half22float2(h3[k]);
            acc[2 * k + 0] = fmaf(f0.x, w0, fmaf(f1.x, w1, fmaf(f2.x, w2, fmaf(f3.x, w3, acc[2 * k + 0]))));
            acc[2 * k + 1] = fmaf(f0.y, w0, fmaf(f1.y, w1, fmaf(f2.y, w2, fmaf(f3.y, w3, acc[2 * k + 1]))));
        }
    }
    for (; j < end; j++) {
        int v = eV[j];
        float w = expf(leakyf(__ldg(&score[v])) - m) * invden;
        uint4 u = __ldg(reinterpret_cast<const uint4*>(Xfeat + (size_t)v * H) + lane);
        const __half2* h = reinterpret_cast<const __half2*>(&u);
#pragma unroll
        for (int k = 0; k < 4; k++) {
            float2 f = __half22float2(h[k]);
            acc[2 * k + 0] = fmaf(f.x, w, acc[2 * k + 0]);
            acc[2 * k + 1] = fmaf(f.y, w, acc[2 * k + 1]);
        }
    }

    uint4 u;
    __half2 p0 = __floats2half2_rn(eluf(acc[0]), eluf(acc[1]));
    __half2 p1 = __floats2half2_rn(eluf(acc[2]), eluf(acc[3]));
    __half2 p2 = __floats2half2_rn(eluf(acc[4]), eluf(acc[5]));
    __half2 p3 = __floats2half2_rn(eluf(acc[6]), eluf(acc[7]));
    u.x = *reinterpret_cast<unsigned*>(&p0);
    u.y = *reinterpret_cast<unsigned*>(&p1);
    u.z = *reinterpret_cast<unsigned*>(&p2);
    u.w = *reinterpret_cast<unsigned*>(&p3);
    *(reinterpret_cast<uint4*>(Ye + (size_t)warp * H) + lane) = u;
}

// ---------------------------------------------------------------------------
// Fused e2v: mean (fp16 gather, x4) + elu + residual (fp16) -> fp16 out
// ---------------------------------------------------------------------------
__global__ __launch_bounds__(256)
void e2v_mean_kernel(const __half* __restrict__ Ye2,
                     const int* __restrict__ v_rowptr, const int* __restrict__ vE,
                     const __half* __restrict__ Xinit,
                     __half* __restrict__ hout, int N, int H)
{
    int warp = (blockIdx.x * blockDim.x + threadIdx.x) >> 5;
    int lane = threadIdx.x & 31;
    if (warp >= N) return;
    const int beg = v_rowptr[warp];
    const int end = v_rowptr[warp + 1];

    float acc[8];
#pragma unroll
    for (int k = 0; k < 8; k++) acc[k] = 0.f;

    int j = beg;
    for (; j + 4 <= end; j += 4) {
        int e0 = vE[j], e1 = vE[j + 1], e2 = vE[j + 2], e3 = vE[j + 3];
        uint4 u0 = __ldg(reinterpret_cast<const uint4*>(Ye2 + (size_t)e0 * H) + lane);
        uint4 u1 = __ldg(reinterpret_cast<const uint4*>(Ye2 + (size_t)e1 * H) + lane);
        uint4 u2 = __ldg(reinterpret_cast<const uint4*>(Ye2 + (size_t)e2 * H) + lane);
        uint4 u3 = __ldg(reinterpret_cast<const uint4*>(Ye2 + (size_t)e3 * H) + lane);
        const __half2* h0 = reinterpret_cast<const __half2*>(&u0);
        const __half2* h1 = reinterpret_cast<const __half2*>(&u1);
        const __half2* h2 = reinterpret_cast<const __half2*>(&u2);
        const __half2* h3 = reinterpret_cast<const __half2*>(&u3);
#pragma unroll
        for (int k = 0; k < 4; k++) {
            float2 f0 = __half22float2(h0[k]);
            float2 f1 = __half22float2(h1[k]);
            float2 f2 = __half22float2(h2[k]);
            float2 f3 = __half22float2(h3[k]);
            acc[2 * k + 0] += (f0.x + f1.x) + (f2.x + f3.x);
            acc[2 * k + 1] += (f0.y + f1.y) + (f2.y + f3.y);
        }
    }
    for (; j < end; j++) {
        int e = vE[j];
        uint4 u = __ldg(reinterpret_cast<const uint4*>(Ye2 + (size_t)e * H) + lane);
        const __half2* h = reinterpret_cast<const __half2*>(&u);
#pragma unroll
        for (int k = 0; k < 4; k++) {
            float2 f = __half22float2(h[k]);
            acc[2 * k + 0] += f.x;
            acc[2 * k + 1] += f.y;
        }
    }
    float inv = (end > beg) ? 1.f / (float)(end - beg) : 0.f;

    uint4 ri = __ldg(reinterpret_cast<const uint4*>(Xinit + (size_t)warp * H) + lane);
    const __half2* rh = reinterpret_cast<const __half2*>(&ri);
    float o[8];
#pragma unroll
    for (int k = 0; k < 4; k++) {
        float2 r = __half22float2(rh[k]);
        o[2 * k + 0] = eluf(acc[2 * k + 0] * inv) + r.x;
        o[2 * k + 1] = eluf(acc[2 * k + 1] * inv) + r.y;
    }

    uint4 u;
    __half2 p0 = __floats2half2_rn(o[0], o[1]);
    __half2 p1 = __floats2half2_rn(o[2], o[3]);
    __half2 p2 = __floats2half2_rn(o[4], o[5]);
    __half2 p3 = __floats2half2_rn(o[6], o[7]);
    u.x = *reinterpret_cast<unsigned*>(&p0);
    u.y = *reinterpret_cast<unsigned*>(&p1);
    u.z = *reinterpret_cast<unsigned*>(&p2);
    u.w = *reinterpret_cast<unsigned*>(&p3);
    *(reinterpret_cast<uint4*>(hout + (size_t)warp * H) + lane) = u;
}

// ---------------------------------------------------------------------------
// Hyperconv edge: fp16 gather (x4), fp16 out.  O == 128.
// ---------------------------------------------------------------------------
__global__ __launch_bounds__(256)
void hyper_edge_kernel(const __half* __restrict__ Xn,
                       const int* __restrict__ e_rowptr, const int* __restrict__ eV,
                       const int* __restrict__ v_rowptr,
                       __half* __restrict__ Ye, int M, int O)
{
    int warp = (blockIdx.x * blockDim.x + threadIdx.x) >> 5;
    int lane = threadIdx.x & 31;
    if (warp >= M) return;
    const int beg = e_rowptr[warp];
    const int end = e_rowptr[warp + 1];
    const int cnt = end - beg;

    float sumDv = 0.f;
    for (int j = beg + lane; j < end; j += 32) {
        int v = eV[j];
        sumDv += (float)(__ldg(&v_rowptr[v + 1]) - __ldg(&v_rowptr[v]));
    }
#pragma unroll
    for (int o = 16; o > 0; o >>= 1) sumDv += __shfl_xor_sync(0xffffffffu, sumDv, o);

    float acc[4];
#pragma unroll
    for (int k = 0; k < 4; k++) acc[k] = 0.f;

    int j = beg;
    for (; j + 4 <= end; j += 4) {
        int v0 = eV[j], v1 = eV[j + 1], v2 = eV[j + 2], v3 = eV[j + 3];
        uint2 u0 = __ldg(reinterpret_cast<const uint2*>(Xn + (size_t)v0 * O) + lane);
        uint2 u1 = __ldg(reinterpret_cast<const uint2*>(Xn + (size_t)v1 * O) + lane);
        uint2 u2 = __ldg(reinterpret_cast<const uint2*>(Xn + (size_t)v2 * O) + lane);
        uint2 u3 = __ldg(reinterpret_cast<const uint2*>(Xn + (size_t)v3 * O) + lane);
        const __half2* h0 = reinterpret_cast<const __half2*>(&u0);
        const __half2* h1 = reinterpret_cast<const __half2*>(&u1);
        const __half2* h2 = reinterpret_cast<const __half2*>(&u2);
        const __half2* h3 = reinterpret_cast<const __half2*>(&u3);
#pragma unroll
        for (int k = 0; k < 2; k++) {
            float2 f0 = __half22float2(h0[k]);
            float2 f1 = __half22float2(h1[k]);
            float2 f2 = __half22float2(h2[k]);
            float2 f3 = __half22float2(h3[k]);
            acc[2 * k + 0] += (f0.x + f1.x) + (f2.x + f3.x);
            acc[2 * k + 1] += (f0.y + f1.y) + (f2.y + f3.y);
        }
    }
    for (; j < end; j++) {
        int v = eV[j];
        uint2 u = __ldg(reinterpret_cast<const uint2*>(Xn + (size_t)v * O) + lane);
        const __half2* h = reinterpret_cast<const __half2*>(&u);
        float2 f0 = __half22float2(h[0]), f1 = __half22float2(h[1]);
        acc[0] += f0.x; acc[1] += f0.y; acc[2] += f1.x; acc[3] += f1.y;
    }

    float invc = (cnt > 0) ? 1.f / (float)cnt : 0.f;
    float De = sumDv / ((float)cnt + 1.f);
    float dinv = (De > 0.f) ? rsqrtf(De) : 1.f;
    float s = invc * dinv;

    uint2 u;
    __half2 p0 = __floats2half2_rn(acc[0] * s, acc[1] * s);
    __half2 p1 = __floats2half2_rn(acc[2] * s, acc[3] * s);
    u.x = *reinterpret_cast<unsigned*>(&p0);
    u.y = *reinterpret_cast<unsigned*>(&p1);
    *(reinterpret_cast<uint2*>(Ye + (size_t)warp * O) + lane) = u;
}

// ---------------------------------------------------------------------------
// Hyperconv node: fp16 gather (x4), fp32 out (final output)
// ---------------------------------------------------------------------------
__global__ __launch_bounds__(256)
void hyper_node_kernel(const __half* __restrict__ Ye,
                       const int* __restrict__ v_rowptr, const int* __restrict__ vE,
                       float* __restrict__ out, int N, int O)
{
    int warp = (blockIdx.x * blockDim.x + threadIdx.x) >> 5;
    int lane = threadIdx.x & 31;
    if (warp >= N) return;
    const int beg = v_rowptr[warp];
    const int end = v_rowptr[warp + 1];
    const int deg = end - beg;

    float acc[4];
#pragma unroll
    for (int k = 0; k < 4; k++) acc[k] = 0.f;

    int j = beg;
    for (; j + 4 <= end; j += 4) {
        int e0 = vE[j], e1 = vE[j + 1], e2 = vE[j + 2], e3 = vE[j + 3];
        uint2 u0 = __ldg(reinterpret_cast<const uint2*>(Ye + (size_t)e0 * O) + lane);
        uint2 u1 = __ldg(reinterpret_cast<const uint2*>(Ye + (size_t)e1 * O) + lane);
        uint2 u2 = __ldg(reinterpret_cast<const uint2*>(Ye + (size_t)e2 * O) + lane);
        uint2 u3 = __ldg(reinterpret_cast<const uint2*>(Ye + (size_t)e3 * O) + lane);
        const __half2* h0 = reinterpret_cast<const __half2*>(&u0);
        const __half2* h1 = reinterpret_cast<const __half2*>(&u1);
        const __half2* h2 = reinterpret_cast<const __half2*>(&u2);
        const __half2* h3 = reinterpret_cast<const __half2*>(&u3);
#pragma unroll
        for (int k = 0; k < 2; k++) {
            float2 f0 = __half22float2(h0[k]);
            float2 f1 = __half22float2(h1[k]);
            float2 f2 = __half22float2(h2[k]);
            float2 f3 = __half22float2(h3[k]);
            acc[2 * k + 0] += (f0.x + f1.x) + (f2.x + f3.x);
            acc[2 * k + 1] += (f0.y + f1.y) + (f2.y + f3.y);
        }
    }
    for (; j < end; j++) {
        int e = vE[j];
        uint2 u = __ldg(reinterpret_cast<const uint2*>(Ye + (size_t)e * O) + lane);
        const __half2* h = reinterpret_cast<const __half2*>(&u);
        float2 f0 = __half22float2(h[0]), f1 = __half22float2(h[1]);
        acc[0] += f0.x; acc[1] += f0.y; acc[2] += f1.x; acc[3] += f1.y;
    }
    float dinv = (deg > 0) ? rsqrtf((float)deg) : 0.f;

    float4 o;
    o.x = acc[0] * dinv; o.y = acc[1] * dinv;
    o.z = acc[2] * dinv; o.w = acc[3] * dinv;
    *(reinterpret_cast<float4*>(out + (size_t)warp * O) + lane) = o;
}

// ---------------------------------------------------------------------------
// Host
// ---------------------------------------------------------------------------
static inline int ceil_div(int a, int b) { return (a + b - 1) / b; }

extern "C" void kernel_launch(void* const* d_in, const int* in_sizes, int n_in,
                              void* d_out, int out_size)
{
    const float* X   = (const float*)d_in[0];
    const int*   V   = (const int*)  d_in[1];
    const int*   E   = (const int*)  d_in[2];
    const float* S   = (const float*)d_in[3];
    const float* Wx0 = (const float*)d_in[4];
    const float* bx0 = (const float*)d_in[5];
    const float* Wv0 = (const float*)d_in[6];
    const float* bv0 = (const float*)d_in[7];
    const float* a0  = (const float*)d_in[8];
    const float* Wt0 = (const float*)d_in[9];
    const float* bt0 = (const float*)d_in[10];
    const float* Wx1 = (const float*)d_in[11];
    const float* bx1 = (const float*)d_in[12];
    const float* Wv1 = (const float*)d_in[13];
    const float* bv1 = (const float*)d_in[14];
    const float* a1  = (const float*)d_in[15];
    const float* Wt1 = (const float*)d_in[16];
    const float* bt1 = (const float*)d_in[17];
    const float* Wf  = (const float*)d_in[18];
    const float* bf  = (const float*)d_in[19];

    const int H    = in_sizes[5];              // 256
    const int IN   = in_sizes[4] / H;          // 128
    const int N    = in_sizes[0] / IN;         // 50000
    const int NNZ  = in_sizes[1];              // 400000
    const int HS   = in_sizes[9] / H;          // 320
    const int STAR = HS - H;                   // 64
    const int M    = in_sizes[3] / STAR;       // 20000
    const int OUT  = in_sizes[19];             // 128

    void* p;
    cudaGetSymbolAddress(&p, g_score0); float* score0 = (float*)p;
    cudaGetSymbolAddress(&p, g_score1); float* score1 = (float*)p;
    cudaGetSymbolAddress(&p, g_Xinit); __half* Xinit = (__half*)p;
    cudaGetSymbolAddress(&p, g_Xfeat); __half* Xfeat = (__half*)p;
    cudaGetSymbolAddress(&p, g_Ye2);   __half* Ye2   = (__half*)p;
    cudaGetSymbolAddress(&p, g_A);  __half* Abuf = (__half*)p;
    cudaGetSymbolAddress(&p, g_B);  __half* Bbuf = (__half*)p;
    cudaGetSymbolAddress(&p, g_Ye); __half* Yeh  = (__half*)p;
    cudaGetSymbolAddress(&p, g_S);  __half* Sh   = (__half*)p;
    cudaGetSymbolAddress(&p, g_Wh); __half* Wh   = (__half*)p;
    cudaGetSymbolAddress(&p, g_e_rowptr); int* e_rowptr = (int*)p;
    cudaGetSymbolAddress(&p, g_v_rowptr); int* v_rowptr = (int*)p;
    cudaGetSymbolAddress(&p, g_e_cursor); int* e_cursor = (int*)p;
    cudaGetSymbolAddress(&p, g_v_cursor); int* v_cursor = (int*)p;
    cudaGetSymbolAddress(&p, g_cntE);     int* cntE     = (int*)p;
    cudaGetSymbolAddress(&p, g_cntV);     int* cntV     = (int*)p;
    cudaGetSymbolAddress(&p, g_eV);       int* eV       = (int*)p;
    cudaGetSymbolAddress(&p, g_vE);       int* vE       = (int*)p;
    cudaGetSymbolAddress(&p, g_bsumE);    int* bsumE    = (int*)p;
    cudaGetSymbolAddress(&p, g_bsumV);    int* bsumV    = (int*)p;

    // one-time init
    static bool inited = false;
    static cudaStream_t s1 = 0, s2 = 0;
    static cudaEvent_t evFork, eWall, eCsr, eCsrV, eG1a, eX0, eG1b, eX1;
    if (!inited) {
        cudaFuncSetAttribute(gemm_fp16, cudaFuncAttributeMaxDynamicSharedMemorySize, GEMM_SMEM);
        int prLo = 0, prHi = 0;
        cudaDeviceGetStreamPriorityRange(&prLo, &prHi);
        if (cudaStreamCreateWithPriority(&s1, cudaStreamNonBlocking, prHi) != cudaSuccess) s1 = 0;
        if (cudaStreamCreateWithPriority(&s2, cudaStreamNonBlocking, prHi) != cudaSuccess) s2 = 0;
        cudaEventCreateWithFlags(&evFork, cudaEventDisableTiming);
        cudaEventCreateWithFlags(&eWall, cudaEventDisableTiming);
        cudaEventCreateWithFlags(&eCsr,  cudaEventDisableTiming);
        cudaEventCreateWithFlags(&eCsrV, cudaEventDisableTiming);
        cudaEventCreateWithFlags(&eG1a,  cudaEventDisableTiming);
        cudaEventCreateWithFlags(&eX0,   cudaEventDisableTiming);
        cudaEventCreateWithFlags(&eG1b,  cudaEventDisableTiming);
        cudaEventCreateWithFlags(&eX1,   cudaEventDisableTiming);
        inited = true;
    }

    // weight offsets ([K,N] row-major, packed)
    const size_t o_wx0 = 0;
    const size_t o_wv0 = o_wx0 + (size_t)IN * H;
    const size_t o_wt0 = o_wv0 + (size_t)IN * H;
    const size_t o_wx1 = o_wt0 + (size_t)HS * H;
    const size_t o_wv1 = o_wx1 + (size_t)H * H;
    const size_t o_wt1 = o_wv1 + (size_t)H * H;
    const size_t o_wf  = o_wt1 + (size_t)HS * H;

    auto gemm = [&](const __half* a1, int K1, const __half* a2, int K2,
                    size_t woff, const float* bias, __half* C, int Mrows, int Ncols,
                    const float* avec, float* sc, cudaStream_t st) {
        dim3 grid(Ncols / 128, ceil_div(Mrows, 128));
        gemm_fp16<<<grid, 256, GEMM_SMEM, st>>>(a1, K1, a2, K2,
            Wh + woff, bias, C, avec, sc, Mrows, Ncols);
    };

    const int nnzBlocks      = ceil_div(NNZ, 256);
    const int edgeWarpBlocks = ceil_div(M, 8);
    const int nodeWarpBlocks = ceil_div(N, 8);
    const int nTilesE = ceil_div(M, SCAN_TILE);   // 5
    const int nTilesV = ceil_div(N, SCAN_TILE);   // 13
    const int nTilesMax = nTilesE > nTilesV ? nTilesE : nTilesV;

    // ---- fork ----
    cudaEventRecord(evFork, 0);
    cudaStreamWaitEvent(s1, evFork, 0);
    cudaStreamWaitEvent(s2, evFork, 0);

    // ---- s2: ONE kernel for all weight/S conversions + both score zeros ----
    {
        ConvJobs jobs;
        jobs.j[0] = { Wv0, Wh + o_wv0, (long)IN * H / 4 };
        jobs.j[1] = { Wx0, Wh + o_wx0, (long)IN * H / 4 };
        jobs.j[2] = { Wt0, Wh + o_wt0, (long)HS * H / 4 };
        jobs.j[3] = { Wx1, Wh + o_wx1, (long)H * H / 4 };
        jobs.j[4] = { Wv1, Wh + o_wv1, (long)H * H / 4 };
        jobs.j[5] = { Wt1, Wh + o_wt1, (long)HS * H / 4 };
        jobs.j[6] = { Wf,  Wh + o_wf,  (long)H * OUT / 4 };
        jobs.j[7] = { S,   Sh,         (long)M * STAR / 4 };
        jobs.sc0 = score0; jobs.sc1 = score1; jobs.n_sc = N;
        dim3 grid(80, 9);
        conv_pack_kernel<<<grid, 256, 0, s2>>>(jobs);
        cudaEventRecord(eWall, s2);
    }

    // ---- s1: CSR build (multi-block 3-phase scan) ----
    fill2_int<<<ceil_div(N, 256), 256, 0, s1>>>(cntE, M, cntV, N);
    count_kernel<<<nnzBlocks, 256, 0, s1>>>(V, E, cntV, cntE, NNZ);
    {
        dim3 gA(nTilesMax, 2);
        scanA_kernel<<<gA, 256, 0, s1>>>(cntE, M, bsumE, cntV, N, bsumV);
        scanB_kernel<<<1, 64, 0, s1>>>(bsumE, nTilesE, bsumV, nTilesV);
        dim3 gC(nTilesMax, 2);
        scanC_kernel<<<gC, 256, 0, s1>>>(cntE, e_rowptr, e_cursor, M, bsumE, nTilesE,
                                         cntV, v_rowptr, v_cursor, N, bsumV, nTilesV);
    }
    fill_eV_kernel<<<nnzBlocks, 256, 0, s1>>>(V, E, e_cursor, eV, NNZ);
    cudaEventRecord(eCsr, s1);
    fill_vE_kernel<<<nnzBlocks, 256, 0, s1>>>(V, E, v_cursor, vE, NNZ);
    cudaEventRecord(eCsrV, s1);

    // ---- s0: convert X, then layer 0 ----
    {
        long n4 = (long)N * IN / 4;
        int blocks = (int)((n4 + 255) / 256); if (blocks > 2048) blocks = 2048;
        tohalf_kernel<<<blocks, 256>>>(X, Abuf, n4);
    }
    cudaStreamWaitEvent(0, eWall, 0);
    gemm(Abuf, IN, nullptr, 0, o_wv0, bv0, Xfeat, N, H, a0, score0, 0);   // Wv0 + fused score
    cudaEventRecord(eG1a, 0);

    cudaStreamWaitEvent(s1, eG1a, 0);
    gemm(Abuf, IN, nullptr, 0, o_wx0, bx0, Xinit, N, H, nullptr, nullptr, s1);
    cudaEventRecord(eX0, s1);

    cudaStreamWaitEvent(0, eCsr, 0);
    v2e_softmax_kernel<<<edgeWarpBlocks, 256>>>(Xfeat, score0, e_rowptr, eV, Yeh, M, H);
    gemm(Yeh, H, Sh, STAR, o_wt0, bt0, Ye2, M, H, nullptr, nullptr, 0);
    cudaStreamWaitEvent(0, eX0, 0);
    cudaStreamWaitEvent(0, eCsrV, 0);
    e2v_mean_kernel<<<nodeWarpBlocks, 256>>>(Ye2, v_rowptr, vE, Xinit, Bbuf, N, H);

    // ---- layer 1 ----
    gemm(Bbuf, H, nullptr, 0, o_wv1, bv1, Xfeat, N, H, a1, score1, 0);
    cudaEventRecord(eG1b, 0);

    cudaStreamWaitEvent(s1, eG1b, 0);
    gemm(Bbuf, H, nullptr, 0, o_wx1, bx1, Xinit, N, H, nullptr, nullptr, s1);
    cudaEventRecord(eX1, s1);

    v2e_softmax_kernel<<<edgeWarpBlocks, 256>>>(Xfeat, score1, e_rowptr, eV, Yeh, M, H);
    gemm(Yeh, H, Sh, STAR, o_wt1, bt1, Ye2, M, H, nullptr, nullptr, 0);
    cudaStreamWaitEvent(0, eX1, 0);
    e2v_mean_kernel<<<nodeWarpBlocks, 256>>>(Ye2, v_rowptr, vE, Xinit, Abuf, N, H);

    // ---- hyperconv (s0) ----
    gemm(Abuf, H, nullptr, 0, o_wf, bf, Xfeat, N, OUT, nullptr, nullptr, 0);
    hyper_edge_kernel<<<edgeWarpBlocks, 256>>>(Xfeat, e_rowptr, eV, v_rowptr, Yeh, M, OUT);
    hyper_node_kernel<<<nodeWarpBlocks, 256>>>(Yeh, v_rowptr, vE, (float*)d_out, N, OUT);
}

// round 16
// speedup vs baseline: 1.0098x; 1.0098x over previous
#include <cuda_runtime.h>
#include <cuda_fp16.h>
#include <mma.h>
#include <math.h>
#include <stdint.h>

using namespace nvcuda;

// ---------------------------------------------------------------------------
// Problem max sizes
// ---------------------------------------------------------------------------
#define NMAX   50000
#define MMAX   20000
#define NNZMAX 400000
#define HMAX   256
#define WTOTAL 393216
#define SCAN_TILE 4096
#define SCAN_MAXTILES 16

// ---------------------------------------------------------------------------
// Scratch (device globals)
// ---------------------------------------------------------------------------
__device__ float g_score0[NMAX];
__device__ float g_score1[NMAX];
__device__ float g_eScale[MMAX];

__device__ __half g_Xinit[NMAX * HMAX];
__device__ __half g_Xfeat[NMAX * HMAX];
__device__ __half g_Ye2  [MMAX * HMAX];
__device__ __half g_A [NMAX * HMAX];
__device__ __half g_B [NMAX * HMAX];
__device__ __half g_Ye[MMAX * HMAX];
__device__ __half g_S [MMAX * 64];
__device__ __half g_Wh[WTOTAL];

// CSR structures
__device__ int g_e_rowptr[MMAX + 1];
__device__ int g_v_rowptr[NMAX + 1];
__device__ int g_e_cursor[MMAX];
__device__ int g_v_cursor[NMAX];
__device__ int g_cntE[MMAX];
__device__ int g_cntV[NMAX];
__device__ int g_eV[NNZMAX];
__device__ int g_vE[NNZMAX];
__device__ int g_bsumE[SCAN_MAXTILES];
__device__ int g_bsumV[SCAN_MAXTILES];

// ---------------------------------------------------------------------------
// Helpers
// ---------------------------------------------------------------------------
__device__ __forceinline__ float eluf(float x)  { return x > 0.f ? x : expm1f(x); }
__device__ __forceinline__ float leakyf(float x){ return x > 0.f ? x : 0.2f * x; }

__device__ __forceinline__ uint32_t smem_to_u32(const void* p) {
    uint32_t a;
    asm("{ .reg .u64 t; cvta.to.shared.u64 t, %1; cvt.u32.u64 %0, t; }" : "=r"(a) : "l"(p));
    return a;
}
__device__ __forceinline__ void cp_async16(uint32_t dst, const void* src, int sz) {
    asm volatile("cp.async.cg.shared.global [%0], [%1], 16, %2;"
                 :: "r"(dst), "l"(src), "r"(sz) : "memory");
}
#define CP_COMMIT() asm volatile("cp.async.commit_group;" ::: "memory")
#define CP_WAIT(n)  asm volatile("cp.async.wait_group %0;" :: "n"(n) : "memory")

__device__ __forceinline__ void conv_store4(float4 v, __half* p) {
    __half2 h0 = __floats2half2_rn(v.x, v.y);
    __half2 h1 = __floats2half2_rn(v.z, v.w);
    uint2 u;
    u.x = *reinterpret_cast<unsigned*>(&h0);
    u.y = *reinterpret_cast<unsigned*>(&h1);
    *reinterpret_cast<uint2*>(p) = u;
}

__global__ void tohalf_kernel(const float* __restrict__ x, __half* __restrict__ out, long n4)
{
    long i = (long)blockIdx.x * blockDim.x + threadIdx.x;
    long stride = (long)gridDim.x * blockDim.x;
    for (; i < n4; i += stride)
        conv_store4(reinterpret_cast<const float4*>(x)[i], out + 4 * i);
}

struct ConvJob { const float* src; __half* dst; long n4; };
struct ConvJobs {
    ConvJob j[8];
    float* sc0; float* sc1; int n_sc;
};
__global__ void conv_pack_kernel(ConvJobs jobs)
{
    int job = blockIdx.y;
    long i = (long)blockIdx.x * blockDim.x + threadIdx.x;
    long stride = (long)gridDim.x * blockDim.x;
    if (job < 8) {
        const float* src = jobs.j[job].src;
        __half* dst = jobs.j[job].dst;
        long n4 = jobs.j[job].n4;
        for (; i < n4; i += stride)
            conv_store4(reinterpret_cast<const float4*>(src)[i], dst + 4 * i);
    } else {
        for (; i < jobs.n_sc; i += stride) {
            jobs.sc0[i] = 0.f;
            jobs.sc1[i] = 0.f;
        }
    }
}

__global__ void fill2_int(int* __restrict__ p0, int n0, int* __restrict__ p1, int n1)
{
    int i = blockIdx.x * blockDim.x + threadIdx.x;
    int stride = gridDim.x * blockDim.x;
    for (int k = i; k < n0; k += stride) p0[k] = 0;
    for (int k = i; k < n1; k += stride) p1[k] = 0;
}

// ---------------------------------------------------------------------------
// CSR construction
// ---------------------------------------------------------------------------
__global__ void count_kernel(const int* __restrict__ V, const int* __restrict__ E,
                             int* __restrict__ cntV, int* __restrict__ cntE, int nnz)
{
    int i = blockIdx.x * blockDim.x + threadIdx.x;
    if (i >= nnz) return;
    atomicAdd(&cntE[E[i]], 1);
    atomicAdd(&cntV[V[i]], 1);
}

__global__ __launch_bounds__(256)
void scanA_kernel(const int* __restrict__ cntE, int lenE, int* __restrict__ bsumE,
                  const int* __restrict__ cntV, int lenV, int* __restrict__ bsumV)
{
    const int* cnt = blockIdx.y ? cntV : cntE;
    int len = blockIdx.y ? lenV : lenE;
    int* bsum = blockIdx.y ? bsumV : bsumE;
    int tile = blockIdx.x;
    int beg = tile * SCAN_TILE;
    if (beg >= len) return;
    int lim = beg + SCAN_TILE < len ? beg + SCAN_TILE : len;

    const int tid = threadIdx.x, lane = tid & 31, wid = tid >> 5;
    int s = 0;
    for (int i = beg + tid * 4; i < lim; i += 1024) {
        int4 v = *reinterpret_cast<const int4*>(cnt + i);
        s += v.x + v.y + v.z + v.w;
    }
#pragma unroll
    for (int o = 16; o > 0; o >>= 1) s += __shfl_xor_sync(0xffffffffu, s, o);
    __shared__ int ws[8];
    if (lane == 0) ws[wid] = s;
    __syncthreads();
    if (tid == 0) {
        int t = 0;
#pragma unroll
        for (int k = 0; k < 8; k++) t += ws[k];
        bsum[tile] = t;
    }
}

__global__ void scanB_kernel(int* __restrict__ bsumE, int nE,
                             int* __restrict__ bsumV, int nV)
{
    int lane = threadIdx.x & 31;
    if (threadIdx.x < 32) {
        int v = (lane < nE) ? bsumE[lane] : 0;
#pragma unroll
        for (int o = 1; o < 32; o <<= 1) {
            int u = __shfl_up_sync(0xffffffffu, v, o);
            if (lane >= o) v += u;
        }
        if (lane < nE) bsumE[lane] = v;
    } else {
        int v = (lane < nV) ? bsumV[lane] : 0;
#pragma unroll
        for (int o = 1; o < 32; o <<= 1) {
            int u = __shfl_up_sync(0xffffffffu, v, o);
            if (lane >= o) v += u;
        }
        if (lane < nV) bsumV[lane] = v;
    }
}

__global__ __launch_bounds__(256)
void scanC_kernel(const int* __restrict__ cntE, int* __restrict__ e_rowptr,
                  int* __restrict__ e_cursor, int lenE, const int* __restrict__ bsumE, int nE,
                  const int* __restrict__ cntV, int* __restrict__ v_rowptr,
                  int* __restrict__ v_cursor, int lenV, const int* __restrict__ bsumV, int nV)
{
    const int* cnt; int* rowptr; int* cursor; int len; const int* bsum; int nb;
    if (blockIdx.y) { cnt = cntV; rowptr = v_rowptr; cursor = v_cursor; len = lenV; bsum = bsumV; nb = nV; }
    else            { cnt = cntE; rowptr = e_rowptr; cursor = e_cursor; len = lenE; bsum = bsumE; nb = nE; }
    int tile = blockIdx.x;
    int beg = tile * SCAN_TILE;
    if (beg >= len) return;
    int lim = beg + SCAN_TILE < len ? beg + SCAN_TILE : len;
    int tbase = (tile == 0) ? 0 : bsum[tile - 1];

    const int tid = threadIdx.x, lane = tid & 31, wid = tid >> 5;
    const int wbeg = beg + wid * 512;
    const int wlim = (wbeg + 512 < lim) ? wbeg + 512 : lim;

    __shared__ int ws[9];
    int s = 0;
    for (int i = wbeg + lane * 4; i < wlim; i += 128) {
        int4 v = *reinterpret_cast<const int4*>(cnt + i);
        s += v.x + v.y + v.z + v.w;
    }
#pragma unroll
    for (int o = 16; o > 0; o >>= 1) s += __shfl_xor_sync(0xffffffffu, s, o);
    if (lane == 0) ws[wid + 1] = s;
    if (tid == 0) ws[0] = 0;
    __syncthreads();
    if (tid == 0) {
#pragma unroll
        for (int k = 1; k < 9; k++) ws[k] += ws[k - 1];
    }
    __syncthreads();

    int carry = tbase + ws[wid];
    int i = wbeg + lane * 4;
    int4 v = (i < wlim) ? *reinterpret_cast<const int4*>(cnt + i) : make_int4(0, 0, 0, 0);
    for (int i0 = wbeg; i0 < wlim; i0 += 128) {
        int inext = i + 128;
        int4 vn = (inext < wlim) ? *reinterpret_cast<const int4*>(cnt + inext)
                                 : make_int4(0, 0, 0, 0);
        int t1 = v.x + v.y, t2 = t1 + v.z, t3 = t2 + v.w;
        int inc = t3;
#pragma unroll
        for (int o = 1; o < 32; o <<= 1) {
            int u = __shfl_up_sync(0xffffffffu, inc, o);
            if (lane >= o) inc += u;
        }
        int excl = carry + inc - t3;
        if (i < wlim) {
            rowptr[i + 0] = excl;       cursor[i + 0] = excl;
            rowptr[i + 1] = excl + v.x; cursor[i + 1] = excl + v.x;
            rowptr[i + 2] = excl + t1;  cursor[i + 2] = excl + t1;
            rowptr[i + 3] = excl + t2;  cursor[i + 3] = excl + t2;
        }
        carry += __shfl_sync(0xffffffffu, inc, 31);
        v = vn;
        i = inext;
    }
    if (tile == nb - 1 && tid == 0) rowptr[len] = bsum[nb - 1];
}

__global__ void fill_eV_kernel(const int* __restrict__ V, const int* __restrict__ E,
                               int* __restrict__ e_cursor, int* __restrict__ eV, int nnz)
{
    int i = blockIdx.x * blockDim.x + threadIdx.x;
    if (i >= nnz) return;
    int pe = atomicAdd(&e_cursor[E[i]], 1);
    eV[pe] = V[i];
}
__global__ void fill_vE_kernel(const int* __restrict__ V, const int* __restrict__ E,
                               int* __restrict__ v_cursor, int* __restrict__ vE, int nnz)
{
    int i = blockIdx.x * blockDim.x + threadIdx.x;
    if (i >= nnz) return;
    int pv = atomicAdd(&v_cursor[V[i]], 1);
    vE[pv] = E[i];
}

// Per-edge hyperconv scale: eScale[e] = (1/cnt) * De^-1/2, De = sumDv/(cnt+1)
// One warp per edge; runs on s1 off the critical path.
__global__ __launch_bounds__(256)
void escale_kernel(const int* __restrict__ e_rowptr, const int* __restrict__ eV,
                   const int* __restrict__ v_rowptr, float* __restrict__ eScale, int M)
{
    int warp = (blockIdx.x * blockDim.x + threadIdx.x) >> 5;
    int lane = threadIdx.x & 31;
    if (warp >= M) return;
    const int beg = e_rowptr[warp];
    const int end = e_rowptr[warp + 1];
    const int cnt = end - beg;

    float sumDv = 0.f;
    for (int j = beg + lane; j < end; j += 32) {
        int v = eV[j];
        sumDv += (float)(__ldg(&v_rowptr[v + 1]) - __ldg(&v_rowptr[v]));
    }
#pragma unroll
    for (int o = 16; o > 0; o >>= 1) sumDv += __shfl_xor_sync(0xffffffffu, sumDv, o);

    if (lane == 0) {
        float invc = (cnt > 0) ? 1.f / (float)cnt : 0.f;
        float De = sumDv / ((float)cnt + 1.f);
        float dinv = (De > 0.f) ? rsqrtf(De) : 1.f;
        eScale[warp] = invc * dinv;
    }
}

// ---------------------------------------------------------------------------
// fp16 tensor-core GEMM (fp16 weights, fp16 out), cp.async double buffered.
// ---------------------------------------------------------------------------
struct GemmStage {
    __half A[128][40];
    __half B[32][136];
};
static constexpr int GEMM_SMEM = 2 * sizeof(GemmStage);   // 37888

__global__ __launch_bounds__(256, 2)
void gemm_fp16(const __half* __restrict__ A1, int K1,
               const __half* __restrict__ A2, int K2,
               const __half* __restrict__ Bg,
               const float* __restrict__ bias,
               __half* __restrict__ Ch,
               const float* __restrict__ avec, float* __restrict__ score_out,
               int M, int N)
{
    extern __shared__ char smem_raw[];
    GemmStage* st = reinterpret_cast<GemmStage*>(smem_raw);

    const int tid  = threadIdx.x;
    const int wid  = tid >> 5, lane = tid & 31;
    const int wm   = wid >> 1, wn = wid & 1;
    const int row0 = blockIdx.y * 128;
    const int col0 = blockIdx.x * 128;
    const int K = K1 + K2, nch = K >> 5;

    wmma::fragment<wmma::accumulator, 16, 16, 16, float> acc[2][4];
#pragma unroll
    for (int mt = 0; mt < 2; mt++)
#pragma unroll
        for (int nt = 0; nt < 4; nt++) wmma::fill_fragment(acc[mt][nt], 0.f);

    auto prefetch = [&](int c, int s) {
        const int k0 = c * 32;
        const __half* a; int lda, col;
        if (k0 < K1) { a = A1; lda = K1; col = k0; }
        else         { a = A2; lda = K2; col = k0 - K1; }
#pragma unroll
        for (int t = 0; t < 2; t++) {
            int u = tid + t * 256, r = u >> 2, q = u & 3;
            int gr = row0 + r;
            int sz = (gr < M) ? 16 : 0;
            size_t off = (size_t)(gr < M ? gr : 0) * lda + col + q * 8;
            cp_async16(smem_to_u32(&st[s].A[r][q * 8]), a + off, sz);
        }
#pragma unroll
        for (int t = 0; t < 2; t++) {
            int u = tid + t * 256, r = u >> 4, q = u & 15;
            size_t off = (size_t)(k0 + r) * N + col0 + q * 8;
            cp_async16(smem_to_u32(&st[s].B[r][q * 8]), Bg + off, 16);
        }
    };

    prefetch(0, 0);
    CP_COMMIT();

    for (int c = 0; c < nch; c++) {
        const int s = c & 1;
        if (c + 1 < nch) {
            prefetch(c + 1, s ^ 1);
            CP_COMMIT();
            CP_WAIT(1);
        } else {
            CP_WAIT(0);
        }
        __syncthreads();

#pragma unroll
        for (int ks = 0; ks < 2; ks++) {
            wmma::fragment<wmma::matrix_a, 16, 16, 16, __half, wmma::row_major> af[2];
#pragma unroll
            for (int mt = 0; mt < 2; mt++)
                wmma::load_matrix_sync(af[mt], &st[s].A[wm * 32 + mt * 16][ks * 16], 40);
#pragma unroll
            for (int nt = 0; nt < 4; nt++) {
                wmma::fragment<wmma::matrix_b, 16, 16, 16, __half, wmma::row_major> bf;
                wmma::load_matrix_sync(bf, &st[s].B[ks * 16][wn * 64 + nt * 16], 136);
#pragma unroll
                for (int mt = 0; mt < 2; mt++)
                    wmma::mma_sync(acc[mt][nt], af[mt], bf, acc[mt][nt]);
            }
        }
        __syncthreads();
    }

    float* stg = reinterpret_cast<float*>(smem_raw) + wid * 320;
#pragma unroll
    for (int mt = 0; mt < 2; mt++) {
        float sacc = 0.f;
        int grow_last = -1;
#pragma unroll
        for (int nt = 0; nt < 4; nt++) {
            wmma::store_matrix_sync(stg, acc[mt][nt], 20, wmma::mem_row_major);
            __syncwarp();
            int r = lane >> 1, cofs = (lane & 1) * 8;
            int gr = row0 + wm * 32 + mt * 16 + r;
            int gc = col0 + wn * 64 + nt * 16 + cofs;
            grow_last = gr;
            if (gr < M) {
                float o[8];
#pragma unroll
                for (int j = 0; j < 8; j++) o[j] = stg[r * 20 + cofs + j] + __ldg(&bias[gc + j]);
                if (score_out) {
#pragma unroll
                    for (int j = 0; j < 8; j++) sacc += o[j] * __ldg(&avec[gc + j]);
                }
                uint4 u;
                __half2 p0 = __floats2half2_rn(o[0], o[1]);
                __half2 p1 = __floats2half2_rn(o[2], o[3]);
                __half2 p2 = __floats2half2_rn(o[4], o[5]);
                __half2 p3 = __floats2half2_rn(o[6], o[7]);
                u.x = *reinterpret_cast<unsigned*>(&p0);
                u.y = *reinterpret_cast<unsigned*>(&p1);
                u.z = *reinterpret_cast<unsigned*>(&p2);
                u.w = *reinterpret_cast<unsigned*>(&p3);
                *reinterpret_cast<uint4*>(Ch + (size_t)gr * N + gc) = u;
            }
            __syncwarp();
        }
        if (score_out && grow_last >= 0 && grow_last < M)
            atomicAdd(&score_out[grow_last], sacc);
    }
}

// ---------------------------------------------------------------------------
// Fused v2e: ONLINE segment softmax (single pre-pass) + weighted fp16 gather
// + elu -> fp16 out (x4 gather unroll)
// ---------------------------------------------------------------------------
__global__ __launch_bounds__(256)
void v2e_softmax_kernel(const __half* __restrict__ Xfeat, const float* __restrict__ score,
                        const int* __restrict__ e_rowptr, const int* __restrict__ eV,
                        __half* __restrict__ Ye, int M, int H)
{
    int warp = (blockIdx.x * blockDim.x + threadIdx.x) >> 5;
    int lane = threadIdx.x & 31;
    if (warp >= M) return;
    const int beg = e_rowptr[warp];
    const int end = e_rowptr[warp + 1];

    // single pass: per-lane online (m, den)
    float m = -1e30f, den = 0.f;
    for (int j = beg + lane; j < end; j += 32) {
        float sc = leakyf(__ldg(&score[eV[j]]));
        if (sc > m) { den = den * expf(m - sc) + 1.f; m = sc; }
        else        { den += expf(sc - m); }
    }
    // warp merge of (m, den)
#pragma unroll
    for (int o = 16; o > 0; o >>= 1) {
        float mo = __shfl_xor_sync(0xffffffffu, m, o);
        float dn = __shfl_xor_sync(0xffffffffu, den, o);
        float mn = fmaxf(m, mo);
        den = den * expf(m - mn) + dn * expf(mo - mn);
        m = mn;
    }
    float invden = (end > beg) ? 1.f / den : 0.f;

    float acc[8];
#pragma unroll
    for (int k = 0; k < 8; k++) acc[k] = 0.f;

    int j = beg;
    for (; j + 4 <= end; j += 4) {
        int v0 = eV[j], v1 = eV[j + 1], v2 = eV[j + 2], v3 = eV[j + 3];
        float w0 = expf(leakyf(__ldg(&score[v0])) - m) * invden;
        float w1 = expf(leakyf(__ldg(&score[v1])) - m) * invden;
        float w2 = expf(leakyf(__ldg(&score[v2])) - m) * invden;
        float w3 = expf(leakyf(__ldg(&score[v3])) - m) * invden;
        uint4 u0 = __ldg(reinterpret_cast<const uint4*>(Xfeat + (size_t)v0 * H) + lane);
        uint4 u1 = __ldg(reinterpret_cast<const uint4*>(Xfeat + (size_t)v1 * H) + lane);
        uint4 u2 = __ldg(reinterpret_cast<const uint4*>(Xfeat + (size_t)v2 * H) + lane);
        uint4 u3 = __ldg(reinterpret_cast<const uint4*>(Xfeat + (size_t)v3 * H) + lane);
        const __half2* h0 = reinterpret_cast<const __half2*>(&u0);
        const __half2* h1 = reinterpret_cast<const __half2*>(&u1);
        const __half2* h2 = reinterpret_cast<const __half2*>(&u2);
        const __half2* h3 = reinterpret_cast<const __half2*>(&u3);
#pragma unroll
        for (int k = 0; k < 4; k++) {
            float2 f0 = __half22float2(h0[k]);
            float2 f1 = __half22float2(h1[k]);
            float2 f2 = __half22float2(h2[k]);
            float2 f3 = __half22float2(h3[k]);
            acc[2 * k + 0] = fmaf(f0.x, w0, fmaf(f1.x, w1, fmaf(f2.x, w2, fmaf(f3.x, w3, acc[2 * k + 0]))));
            acc[2 * k + 1] = fmaf(f0.y, w0, fmaf(f1.y, w1, fmaf(f2.y, w2, fmaf(f3.y, w3, acc[2 * k + 1]))));
        }
    }
    for (; j < end; j++) {
        int v = eV[j];
        float w = expf(leakyf(__ldg(&score[v])) - m) * invden;
        uint4 u = __ldg(reinterpret_cast<const uint4*>(Xfeat + (size_t)v * H) + lane);
        const __half2* h = reinterpret_cast<const __half2*>(&u);
#pragma unroll
        for (int k = 0; k < 4; k++) {
            float2 f = __half22float2(h[k]);
            acc[2 * k + 0] = fmaf(f.x, w, acc[2 * k + 0]);
            acc[2 * k + 1] = fmaf(f.y, w, acc[2 * k + 1]);
        }
    }

    uint4 u;
    __half2 p0 = __floats2half2_rn(eluf(acc[0]), eluf(acc[1]));
    __half2 p1 = __floats2half2_rn(eluf(acc[2]), eluf(acc[3]));
    __half2 p2 = __floats2half2_rn(eluf(acc[4]), eluf(acc[5]));
    __half2 p3 = __floats2half2_rn(eluf(acc[6]), eluf(acc[7]));
    u.x = *reinterpret_cast<unsigned*>(&p0);
    u.y = *reinterpret_cast<unsigned*>(&p1);
    u.z = *reinterpret_cast<unsigned*>(&p2);
    u.w = *reinterpret_cast<unsigned*>(&p3);
    *(reinterpret_cast<uint4*>(Ye + (size_t)warp * H) + lane) = u;
}

// ---------------------------------------------------------------------------
// Fused e2v: mean (fp16 gather, x4) + elu + residual (fp16) -> fp16 out
// ---------------------------------------------------------------------------
__global__ __launch_bounds__(256)
void e2v_mean_kernel(const __half* __restrict__ Ye2,
                     const int* __restrict__ v_rowptr, const int* __restrict__ vE,
                     const __half* __restrict__ Xinit,
                     __half* __restrict__ hout, int N, int H)
{
    int warp = (blockIdx.x * blockDim.x + threadIdx.x) >> 5;
    int lane = threadIdx.x & 31;
    if (warp >= N) return;
    const int beg = v_rowptr[warp];
    const int end = v_rowptr[warp + 1];

    float acc[8];
#pragma unroll
    for (int k = 0; k < 8; k++) acc[k] = 0.f;

    int j = beg;
    for (; j + 4 <= end; j += 4) {
        int e0 = vE[j], e1 = vE[j + 1], e2 = vE[j + 2], e3 = vE[j + 3];
        uint4 u0 = __ldg(reinterpret_cast<const uint4*>(Ye2 + (size_t)e0 * H) + lane);
        uint4 u1 = __ldg(reinterpret_cast<const uint4*>(Ye2 + (size_t)e1 * H) + lane);
        uint4 u2 = __ldg(reinterpret_cast<const uint4*>(Ye2 + (size_t)e2 * H) + lane);
        uint4 u3 = __ldg(reinterpret_cast<const uint4*>(Ye2 + (size_t)e3 * H) + lane);
        const __half2* h0 = reinterpret_cast<const __half2*>(&u0);
        const __half2* h1 = reinterpret_cast<const __half2*>(&u1);
        const __half2* h2 = reinterpret_cast<const __half2*>(&u2);
        const __half2* h3 = reinterpret_cast<const __half2*>(&u3);
#pragma unroll
        for (int k = 0; k < 4; k++) {
            float2 f0 = __half22float2(h0[k]);
            float2 f1 = __half22float2(h1[k]);
            float2 f2 = __half22float2(h2[k]);
            float2 f3 = __half22float2(h3[k]);
            acc[2 * k + 0] += (f0.x + f1.x) + (f2.x + f3.x);
            acc[2 * k + 1] += (f0.y + f1.y) + (f2.y + f3.y);
        }
    }
    for (; j < end; j++) {
        int e = vE[j];
        uint4 u = __ldg(reinterpret_cast<const uint4*>(Ye2 + (size_t)e * H) + lane);
        const __half2* h = reinterpret_cast<const __half2*>(&u);
#pragma unroll
        for (int k = 0; k < 4; k++) {
            float2 f = __half22float2(h[k]);
            acc[2 * k + 0] += f.x;
            acc[2 * k + 1] += f.y;
        }
    }
    float inv = (end > beg) ? 1.f / (float)(end - beg) : 0.f;

    uint4 ri = __ldg(reinterpret_cast<const uint4*>(Xinit + (size_t)warp * H) + lane);
    const __half2* rh = reinterpret_cast<const __half2*>(&ri);
    float o[8];
#pragma unroll
    for (int k = 0; k < 4; k++) {
        float2 r = __half22float2(rh[k]);
        o[2 * k + 0] = eluf(acc[2 * k + 0] * inv) + r.x;
        o[2 * k + 1] = eluf(acc[2 * k + 1] * inv) + r.y;
    }

    uint4 u;
    __half2 p0 = __floats2half2_rn(o[0], o[1]);
    __half2 p1 = __floats2half2_rn(o[2], o[3]);
    __half2 p2 = __floats2half2_rn(o[4], o[5]);
    __half2 p3 = __floats2half2_rn(o[6], o[7]);
    u.x = *reinterpret_cast<unsigned*>(&p0);
    u.y = *reinterpret_cast<unsigned*>(&p1);
    u.z = *reinterpret_cast<unsigned*>(&p2);
    u.w = *reinterpret_cast<unsigned*>(&p3);
    *(reinterpret_cast<uint4*>(hout + (size_t)warp * H) + lane) = u;
}

// ---------------------------------------------------------------------------
// Hyperconv edge: fp16 gather (x4), fp16 out, precomputed eScale.  O == 128.
// ---------------------------------------------------------------------------
__global__ __launch_bounds__(256)
void hyper_edge_kernel(const __half* __restrict__ Xn,
                       const int* __restrict__ e_rowptr, const int* __restrict__ eV,
                       const float* __restrict__ eScale,
                       __half* __restrict__ Ye, int M, int O)
{
    int warp = (blockIdx.x * blockDim.x + threadIdx.x) >> 5;
    int lane = threadIdx.x & 31;
    if (warp >= M) return;
    const int beg = e_rowptr[warp];
    const int end = e_rowptr[warp + 1];

    float acc[4];
#pragma unroll
    for (int k = 0; k < 4; k++) acc[k] = 0.f;

    int j = beg;
    for (; j + 4 <= end; j += 4) {
        int v0 = eV[j], v1 = eV[j + 1], v2 = eV[j + 2], v3 = eV[j + 3];
        uint2 u0 = __ldg(reinterpret_cast<const uint2*>(Xn + (size_t)v0 * O) + lane);
        uint2 u1 = __ldg(reinterpret_cast<const uint2*>(Xn + (size_t)v1 * O) + lane);
        uint2 u2 = __ldg(reinterpret_cast<const uint2*>(Xn + (size_t)v2 * O) + lane);
        uint2 u3 = __ldg(reinterpret_cast<const uint2*>(Xn + (size_t)v3 * O) + lane);
        const __half2* h0 = reinterpret_cast<const __half2*>(&u0);
        const __half2* h1 = reinterpret_cast<const __half2*>(&u1);
        const __half2* h2 = reinterpret_cast<const __half2*>(&u2);
        const __half2* h3 = reinterpret_cast<const __half2*>(&u3);
#pragma unroll
        for (int k = 0; k < 2; k++) {
            float2 f0 = __half22float2(h0[k]);
            float2 f1 = __half22float2(h1[k]);
            float2 f2 = __half22float2(h2[k]);
            float2 f3 = __half22float2(h3[k]);
            acc[2 * k + 0] += (f0.x + f1.x) + (f2.x + f3.x);
            acc[2 * k + 1] += (f0.y + f1.y) + (f2.y + f3.y);
        }
    }
    for (; j < end; j++) {
        int v = eV[j];
        uint2 u = __ldg(reinterpret_cast<const uint2*>(Xn + (size_t)v * O) + lane);
        const __half2* h = reinterpret_cast<const __half2*>(&u);
        float2 f0 = __half22float2(h[0]), f1 = __half22float2(h[1]);
        acc[0] += f0.x; acc[1] += f0.y; acc[2] += f1.x; acc[3] += f1.y;
    }

    float s = __ldg(&eScale[warp]);

    uint2 u;
    __half2 p0 = __floats2half2_rn(acc[0] * s, acc[1] * s);
    __half2 p1 = __floats2half2_rn(acc[2] * s, acc[3] * s);
    u.x = *reinterpret_cast<unsigned*>(&p0);
    u.y = *reinterpret_cast<unsigned*>(&p1);
    *(reinterpret_cast<uint2*>(Ye + (size_t)warp * O) + lane) = u;
}

// ---------------------------------------------------------------------------
// Hyperconv node: fp16 gather (x4), fp32 out (final output)
// ---------------------------------------------------------------------------
__global__ __launch_bounds__(256)
void hyper_node_kernel(const __half* __restrict__ Ye,
                       const int* __restrict__ v_rowptr, const int* __restrict__ vE,
                       float* __restrict__ out, int N, int O)
{
    int warp = (blockIdx.x * blockDim.x + threadIdx.x) >> 5;
    int lane = threadIdx.x & 31;
    if (warp >= N) return;
    const int beg = v_rowptr[warp];
    const int end = v_rowptr[warp + 1];
    const int deg = end - beg;

    float acc[4];
#pragma unroll
    for (int k = 0; k < 4; k++) acc[k] = 0.f;

    int j = beg;
    for (; j + 4 <= end; j += 4) {
        int e0 = vE[j], e1 = vE[j + 1], e2 = vE[j + 2], e3 = vE[j + 3];
        uint2 u0 = __ldg(reinterpret_cast<const uint2*>(Ye + (size_t)e0 * O) + lane);
        uint2 u1 = __ldg(reinterpret_cast<const uint2*>(Ye + (size_t)e1 * O) + lane);
        uint2 u2 = __ldg(reinterpret_cast<const uint2*>(Ye + (size_t)e2 * O) + lane);
        uint2 u3 = __ldg(reinterpret_cast<const uint2*>(Ye + (size_t)e3 * O) + lane);
        const __half2* h0 = reinterpret_cast<const __half2*>(&u0);
        const __half2* h1 = reinterpret_cast<const __half2*>(&u1);
        const __half2* h2 = reinterpret_cast<const __half2*>(&u2);
        const __half2* h3 = reinterpret_cast<const __half2*>(&u3);
#pragma unroll
        for (int k = 0; k < 2; k++) {
            float2 f0 = __half22float2(h0[k]);
            float2 f1 = __half22float2(h1[k]);
            float2 f2 = __half22float2(h2[k]);
            float2 f3 = __half22float2(h3[k]);
            acc[2 * k + 0] += (f0.x + f1.x) + (f2.x + f3.x);
            acc[2 * k + 1] += (f0.y + f1.y) + (f2.y + f3.y);
        }
    }
    for (; j < end; j++) {
        int e = vE[j];
        uint2 u = __ldg(reinterpret_cast<const uint2*>(Ye + (size_t)e * O) + lane);
        const __half2* h = reinterpret_cast<const __half2*>(&u);
        float2 f0 = __half22float2(h[0]), f1 = __half22float2(h[1]);
        acc[0] += f0.x; acc[1] += f0.y; acc[2] += f1.x; acc[3] += f1.y;
    }
    float dinv = (deg > 0) ? rsqrtf((float)deg) : 0.f;

    float4 o;
    o.x = acc[0] * dinv; o.y = acc[1] * dinv;
    o.z = acc[2] * dinv; o.w = acc[3] * dinv;
    *(reinterpret_cast<float4*>(out + (size_t)warp * O) + lane) = o;
}

// ---------------------------------------------------------------------------
// Host
// ---------------------------------------------------------------------------
static inline int ceil_div(int a, int b) { return (a + b - 1) / b; }

extern "C" void kernel_launch(void* const* d_in, const int* in_sizes, int n_in,
                              void* d_out, int out_size)
{
    const float* X   = (const float*)d_in[0];
    const int*   V   = (const int*)  d_in[1];
    const int*   E   = (const int*)  d_in[2];
    const float* S   = (const float*)d_in[3];
    const float* Wx0 = (const float*)d_in[4];
    const float* bx0 = (const float*)d_in[5];
    const float* Wv0 = (const float*)d_in[6];
    const float* bv0 = (const float*)d_in[7];
    const float* a0  = (const float*)d_in[8];
    const float* Wt0 = (const float*)d_in[9];
    const float* bt0 = (const float*)d_in[10];
    const float* Wx1 = (const float*)d_in[11];
    const float* bx1 = (const float*)d_in[12];
    const float* Wv1 = (const float*)d_in[13];
    const float* bv1 = (const float*)d_in[14];
    const float* a1  = (const float*)d_in[15];
    const float* Wt1 = (const float*)d_in[16];
    const float* bt1 = (const float*)d_in[17];
    const float* Wf  = (const float*)d_in[18];
    const float* bf  = (const float*)d_in[19];

    const int H    = in_sizes[5];              // 256
    const int IN   = in_sizes[4] / H;          // 128
    const int N    = in_sizes[0] / IN;         // 50000
    const int NNZ  = in_sizes[1];              // 400000
    const int HS   = in_sizes[9] / H;          // 320
    const int STAR = HS - H;                   // 64
    const int M    = in_sizes[3] / STAR;       // 20000
    const int OUT  = in_sizes[19];             // 128

    void* p;
    cudaGetSymbolAddress(&p, g_score0); float* score0 = (float*)p;
    cudaGetSymbolAddress(&p, g_score1); float* score1 = (float*)p;
    cudaGetSymbolAddress(&p, g_eScale); float* eScale = (float*)p;
    cudaGetSymbolAddress(&p, g_Xinit); __half* Xinit = (__half*)p;
    cudaGetSymbolAddress(&p, g_Xfeat); __half* Xfeat = (__half*)p;
    cudaGetSymbolAddress(&p, g_Ye2);   __half* Ye2   = (__half*)p;
    cudaGetSymbolAddress(&p, g_A);  __half* Abuf = (__half*)p;
    cudaGetSymbolAddress(&p, g_B);  __half* Bbuf = (__half*)p;
    cudaGetSymbolAddress(&p, g_Ye); __half* Yeh  = (__half*)p;
    cudaGetSymbolAddress(&p, g_S);  __half* Sh   = (__half*)p;
    cudaGetSymbolAddress(&p, g_Wh); __half* Wh   = (__half*)p;
    cudaGetSymbolAddress(&p, g_e_rowptr); int* e_rowptr = (int*)p;
    cudaGetSymbolAddress(&p, g_v_rowptr); int* v_rowptr = (int*)p;
    cudaGetSymbolAddress(&p, g_e_cursor); int* e_cursor = (int*)p;
    cudaGetSymbolAddress(&p, g_v_cursor); int* v_cursor = (int*)p;
    cudaGetSymbolAddress(&p, g_cntE);     int* cntE     = (int*)p;
    cudaGetSymbolAddress(&p, g_cntV);     int* cntV     = (int*)p;
    cudaGetSymbolAddress(&p, g_eV);       int* eV       = (int*)p;
    cudaGetSymbolAddress(&p, g_vE);       int* vE       = (int*)p;
    cudaGetSymbolAddress(&p, g_bsumE);    int* bsumE    = (int*)p;
    cudaGetSymbolAddress(&p, g_bsumV);    int* bsumV    = (int*)p;

    // one-time init
    static bool inited = false;
    static cudaStream_t s1 = 0, s2 = 0;
    static cudaEvent_t evFork, eWall, eCsr, eCsrV, eG1a, eX0, eG1b, eX1;
    if (!inited) {
        cudaFuncSetAttribute(gemm_fp16, cudaFuncAttributeMaxDynamicSharedMemorySize, GEMM_SMEM);
        int prLo = 0, prHi = 0;
        cudaDeviceGetStreamPriorityRange(&prLo, &prHi);
        if (cudaStreamCreateWithPriority(&s1, cudaStreamNonBlocking, prHi) != cudaSuccess) s1 = 0;
        if (cudaStreamCreateWithPriority(&s2, cudaStreamNonBlocking, prHi) != cudaSuccess) s2 = 0;
        cudaEventCreateWithFlags(&evFork, cudaEventDisableTiming);
        cudaEventCreateWithFlags(&eWall, cudaEventDisableTiming);
        cudaEventCreateWithFlags(&eCsr,  cudaEventDisableTiming);
        cudaEventCreateWithFlags(&eCsrV, cudaEventDisableTiming);
        cudaEventCreateWithFlags(&eG1a,  cudaEventDisableTiming);
        cudaEventCreateWithFlags(&eX0,   cudaEventDisableTiming);
        cudaEventCreateWithFlags(&eG1b,  cudaEventDisableTiming);
        cudaEventCreateWithFlags(&eX1,   cudaEventDisableTiming);
        inited = true;
    }

    // weight offsets ([K,N] row-major, packed)
    const size_t o_wx0 = 0;
    const size_t o_wv0 = o_wx0 + (size_t)IN * H;
    const size_t o_wt0 = o_wv0 + (size_t)IN * H;
    const size_t o_wx1 = o_wt0 + (size_t)HS * H;
    const size_t o_wv1 = o_wx1 + (size_t)H * H;
    const size_t o_wt1 = o_wv1 + (size_t)H * H;
    const size_t o_wf  = o_wt1 + (size_t)HS * H;

    auto gemm = [&](const __half* a1, int K1, const __half* a2, int K2,
                    size_t woff, const float* bias, __half* C, int Mrows, int Ncols,
                    const float* avec, float* sc, cudaStream_t st) {
        dim3 grid(Ncols / 128, ceil_div(Mrows, 128));
        gemm_fp16<<<grid, 256, GEMM_SMEM, st>>>(a1, K1, a2, K2,
            Wh + woff, bias, C, avec, sc, Mrows, Ncols);
    };

    const int nnzBlocks      = ceil_div(NNZ, 256);
    const int edgeWarpBlocks = ceil_div(M, 8);
    const int nodeWarpBlocks = ceil_div(N, 8);
    const int nTilesE = ceil_div(M, SCAN_TILE);
    const int nTilesV = ceil_div(N, SCAN_TILE);
    const int nTilesMax = nTilesE > nTilesV ? nTilesE : nTilesV;

    // ---- fork ----
    cudaEventRecord(evFork, 0);
    cudaStreamWaitEvent(s1, evFork, 0);
    cudaStreamWaitEvent(s2, evFork, 0);

    // ---- s2: ONE kernel for all weight/S conversions + both score zeros ----
    {
        ConvJobs jobs;
        jobs.j[0] = { Wv0, Wh + o_wv0, (long)IN * H / 4 };
        jobs.j[1] = { Wx0, Wh + o_wx0, (long)IN * H / 4 };
        jobs.j[2] = { Wt0, Wh + o_wt0, (long)HS * H / 4 };
        jobs.j[3] = { Wx1, Wh + o_wx1, (long)H * H / 4 };
        jobs.j[4] = { Wv1, Wh + o_wv1, (long)H * H / 4 };
        jobs.j[5] = { Wt1, Wh + o_wt1, (long)HS * H / 4 };
        jobs.j[6] = { Wf,  Wh + o_wf,  (long)H * OUT / 4 };
        jobs.j[7] = { S,   Sh,         (long)M * STAR / 4 };
        jobs.sc0 = score0; jobs.sc1 = score1; jobs.n_sc = N;
        dim3 grid(80, 9);
        conv_pack_kernel<<<grid, 256, 0, s2>>>(jobs);
        cudaEventRecord(eWall, s2);
    }

    // ---- s1: CSR build (multi-block 3-phase scan) ----
    fill2_int<<<ceil_div(N, 256), 256, 0, s1>>>(cntE, M, cntV, N);
    count_kernel<<<nnzBlocks, 256, 0, s1>>>(V, E, cntV, cntE, NNZ);
    {
        dim3 gA(nTilesMax, 2);
        scanA_kernel<<<gA, 256, 0, s1>>>(cntE, M, bsumE, cntV, N, bsumV);
        scanB_kernel<<<1, 64, 0, s1>>>(bsumE, nTilesE, bsumV, nTilesV);
        dim3 gC(nTilesMax, 2);
        scanC_kernel<<<gC, 256, 0, s1>>>(cntE, e_rowptr, e_cursor, M, bsumE, nTilesE,
                                         cntV, v_rowptr, v_cursor, N, bsumV, nTilesV);
    }
    fill_eV_kernel<<<nnzBlocks, 256, 0, s1>>>(V, E, e_cursor, eV, NNZ);
    cudaEventRecord(eCsr, s1);
    fill_vE_kernel<<<nnzBlocks, 256, 0, s1>>>(V, E, v_cursor, vE, NNZ);
    escale_kernel<<<edgeWarpBlocks, 256, 0, s1>>>(e_rowptr, eV, v_rowptr, eScale, M);
    cudaEventRecord(eCsrV, s1);

    // ---- s0: convert X, then layer 0 ----
    {
        long n4 = (long)N * IN / 4;
        int blocks = (int)((n4 + 255) / 256); if (blocks > 2048) blocks = 2048;
        tohalf_kernel<<<blocks, 256>>>(X, Abuf, n4);
    }
    cudaStreamWaitEvent(0, eWall, 0);
    gemm(Abuf, IN, nullptr, 0, o_wv0, bv0, Xfeat, N, H, a0, score0, 0);   // Wv0 + fused score
    cudaEventRecord(eG1a, 0);

    cudaStreamWaitEvent(s1, eG1a, 0);
    gemm(Abuf, IN, nullptr, 0, o_wx0, bx0, Xinit, N, H, nullptr, nullptr, s1);
    cudaEventRecord(eX0, s1);

    cudaStreamWaitEvent(0, eCsr, 0);
    v2e_softmax_kernel<<<edgeWarpBlocks, 256>>>(Xfeat, score0, e_rowptr, eV, Yeh, M, H);
    gemm(Yeh, H, Sh, STAR, o_wt0, bt0, Ye2, M, H, nullptr, nullptr, 0);
    cudaStreamWaitEvent(0, eX0, 0);
    cudaStreamWaitEvent(0, eCsrV, 0);
    e2v_mean_kernel<<<nodeWarpBlocks, 256>>>(Ye2, v_rowptr, vE, Xinit, Bbuf, N, H);

    // ---- layer 1 ----
    gemm(Bbuf, H, nullptr, 0, o_wv1, bv1, Xfeat, N, H, a1, score1, 0);
    cudaEventRecord(eG1b, 0);

    cudaStreamWaitEvent(s1, eG1b, 0);
    gemm(Bbuf, H, nullptr, 0, o_wx1, bx1, Xinit, N, H, nullptr, nullptr, s1);
    cudaEventRecord(eX1, s1);

    v2e_softmax_kernel<<<edgeWarpBlocks, 256>>>(Xfeat, score1, e_rowptr, eV, Yeh, M, H);
    gemm(Yeh, H, Sh, STAR, o_wt1, bt1, Ye2, M, H, nullptr, nullptr, 0);
    cudaStreamWaitEvent(0, eX1, 0);
    e2v_mean_kernel<<<nodeWarpBlocks, 256>>>(Ye2, v_rowptr, vE, Xinit, Abuf, N, H);

    // ---- hyperconv (s0) ----
    gemm(Abuf, H, nullptr, 0, o_wf, bf, Xfeat, N, OUT, nullptr, nullptr, 0);
    hyper_edge_kernel<<<edgeWarpBlocks, 256>>>(Xfeat, e_rowptr, eV, eScale, Yeh, M, OUT);
    hyper_node_kernel<<<nodeWarpBlocks, 256>>>(Yeh, v_rowptr, vE, (float*)d_out, N, OUT);
}